// round 4
// baseline (speedup 1.0000x reference)
#include <cuda_runtime.h>
#include <math.h>

constexpr int Bn = 4;
constexpr int Cd = 64;
constexpr int Hh = 256;
constexpr int Ww = 256;
constexpr int HWC = Hh * Ww;      // 65536
constexpr int Wh = 128;
constexpr int Nh = Hh * Wh;       // 32768

// ---------------- scratch (alloc-free: __device__ globals) ----------------
__device__ float g_t  [(size_t)Bn * Cd  * HWC];   //  67 MB  1x1-conv temp
__device__ float g_qs [(size_t)Bn * Cd  * Nh ];   //  33.5MB squeezed q
__device__ float g_ks [(size_t)Bn * Cd  * Nh ];   //  33.5MB squeezed k
__device__ float g_vs [(size_t)Bn * Cd  * Nh ];   //  33.5MB squeezed v
__device__ float g_ctx[Bn * 4 * 256];             //  16 KB  per (b,head) 16x16
__device__ float g_att[(size_t)Bn * Cd  * HWC];   //  67 MB  dense att (zeros at anchor)
__device__ float g_attn[(size_t)Bn * 128 * HWC];  // 134 MB  attention (residual)
__device__ float g_m1 [(size_t)Bn * 256 * HWC];   // 268 MB
__device__ float g_m2 [(size_t)Bn * 256 * HWC];   // 268 MB

__device__ __forceinline__ float gelu_f(float x) {
    return 0.5f * x * (1.0f + erff(x * 0.7071067811865476f));
}

// ---------------- generic 1x1 conv (GEMM per pixel) ----------------
// blockDim 128 (pixels). grid: (HW/128, OC/64, B). ACT: 0 none, 1 gelu, 2 +res
// maskmode: 0 none, 1 keep (i+j) odd (anchor), 2 keep (i+j) even (nonanchor)
template<int IC, int OC, int ACT>
__global__ void __launch_bounds__(128)
conv1x1_k(const float* __restrict__ in, const float* __restrict__ w,
          const float* __restrict__ bias, const float* __restrict__ res,
          float* __restrict__ out, int maskmode)
{
    __shared__ __align__(16) float sW[4096];  // [ci][c] chunk, c contiguous
    const int b   = blockIdx.z;
    const int ocg = blockIdx.y;
    const int p   = blockIdx.x * 128 + threadIdx.x;
    const int i   = p >> 8, j = p & 255;
    const bool keep = (maskmode == 0) || (((i + j) & 1) == (maskmode == 1 ? 1 : 0));

    float acc[64];
#pragma unroll
    for (int c = 0; c < 64; c++) acc[c] = 0.f;

    const float* inb = in + (size_t)b * IC * HWC + p;
    for (int cc = 0; cc < IC; cc += 64) {
        __syncthreads();
        for (int t = threadIdx.x; t < 4096; t += 128) {
            int ci = t >> 6, c = t & 63;
            sW[ci * 64 + c] = w[(size_t)(ocg * 64 + c) * IC + cc + ci];
        }
        __syncthreads();
        for (int ci = 0; ci < 64; ci++) {
            float xv = keep ? inb[(size_t)(cc + ci) * HWC] : 0.f;
#pragma unroll
            for (int c = 0; c < 64; c++)
                acc[c] = fmaf(sW[ci * 64 + c], xv, acc[c]);
        }
    }

    float* outb = out + ((size_t)b * OC + ocg * 64) * HWC + p;
    const float* resb = (ACT == 2) ? (res + ((size_t)b * OC + ocg * 64) * HWC + p) : nullptr;
#pragma unroll
    for (int c = 0; c < 64; c++) {
        float v = acc[c] + __ldg(&bias[ocg * 64 + c]);
        if (ACT == 1) v = gelu_f(v);
        if (ACT == 2) v += resb[(size_t)c * HWC];
        outb[(size_t)c * HWC] = v;
    }
}

// ---------------- depthwise 3x3 + checkerboard squeeze ----------------
// type 0: anchor squeeze  (col = 2*jc + 1-(i&1));  type 1: nonanchor (col = 2*jc + (i&1))
// blockDim 128 (=Wh), grid (H, B*C)
__global__ void dw3x3_squeeze_k(const float* __restrict__ in, const float* __restrict__ w,
                                const float* __restrict__ bias, float* __restrict__ out, int type)
{
    const int i  = blockIdx.x;
    const int bc = blockIdx.y;
    const int c  = bc & 63;
    const int jc = threadIdx.x;
    const int sel = type ? (i & 1) : (1 - (i & 1));
    const int jf  = 2 * jc + sel;
    const float* inp = in + (size_t)bc * HWC;
    float acc = __ldg(&bias[c]);
#pragma unroll
    for (int dy = -1; dy <= 1; dy++) {
        int ii = i + dy;
        if (ii < 0 || ii >= Hh) continue;
#pragma unroll
        for (int dx = -1; dx <= 1; dx++) {
            int jj = jf + dx;
            if (jj < 0 || jj >= Ww) continue;
            acc += __ldg(&w[c * 9 + (dy + 1) * 3 + (dx + 1)]) * inp[ii * Ww + jj];
        }
    }
    out[(size_t)bc * Nh + i * Wh + jc] = acc;
}

// ---------------- depthwise 3x3 + gelu (m2, 256 ch, full width) ----------------
// blockDim 256 (=W), grid (H, B*256)
__global__ void dw3x3_gelu_k(const float* __restrict__ in, const float* __restrict__ w,
                             const float* __restrict__ bias, float* __restrict__ out)
{
    const int i  = blockIdx.x;
    const int bc = blockIdx.y;
    const int c  = bc & 255;
    const int j  = threadIdx.x;
    const float* inp = in + (size_t)bc * HWC;
    float acc = __ldg(&bias[c]);
#pragma unroll
    for (int dy = -1; dy <= 1; dy++) {
        int ii = i + dy;
        if (ii < 0 || ii >= Hh) continue;
#pragma unroll
        for (int dx = -1; dx <= 1; dx++) {
            int jj = j + dx;
            if (jj < 0 || jj >= Ww) continue;
            acc += __ldg(&w[c * 9 + (dy + 1) * 3 + (dx + 1)]) * inp[ii * Ww + jj];
        }
    }
    out[(size_t)bc * HWC + i * Ww + j] = gelu_f(acc);
}

// ---------------- softmax over N=32768 per (b,c) row (k path), in place ----------------
__global__ void softmax_rows_k(float* __restrict__ x)
{
    const size_t base = (size_t)blockIdx.x * Nh;
    __shared__ float red[256];
    float mx = -1e30f;
    for (int n = threadIdx.x; n < Nh; n += 256) mx = fmaxf(mx, x[base + n]);
    red[threadIdx.x] = mx; __syncthreads();
    for (int s = 128; s > 0; s >>= 1) {
        if (threadIdx.x < s) red[threadIdx.x] = fmaxf(red[threadIdx.x], red[threadIdx.x + s]);
        __syncthreads();
    }
    mx = red[0]; __syncthreads();
    float sum = 0.f;
    for (int n = threadIdx.x; n < Nh; n += 256) sum += __expf(x[base + n] - mx);
    red[threadIdx.x] = sum; __syncthreads();
    for (int s = 128; s > 0; s >>= 1) {
        if (threadIdx.x < s) red[threadIdx.x] += red[threadIdx.x + s];
        __syncthreads();
    }
    float inv = 1.0f / red[0];
    for (int n = threadIdx.x; n < Nh; n += 256) x[base + n] = __expf(x[base + n] - mx) * inv;
}

// ---------------- softmax over d=16 channels (q path), in place ----------------
__global__ void softmax_q_k(float* __restrict__ q)
{
    const size_t idx = (size_t)blockIdx.x * 256 + threadIdx.x;  // over B*HEADS*Nh
    const int n  = (int)(idx & (Nh - 1));
    const int bh = (int)(idx >> 15);
    const int b = bh >> 2, hd = bh & 3;
    float* base = q + ((size_t)b * Cd + hd * 16) * Nh + n;
    float v[16]; float mx = -1e30f;
#pragma unroll
    for (int d = 0; d < 16; d++) { v[d] = base[(size_t)d * Nh]; mx = fmaxf(mx, v[d]); }
    float s = 0.f;
#pragma unroll
    for (int d = 0; d < 16; d++) { v[d] = __expf(v[d] - mx); s += v[d]; }
    float inv = 1.0f / s;
#pragma unroll
    for (int d = 0; d < 16; d++) base[(size_t)d * Nh] = v[d] * inv;
}

// ---------------- ctx[b,h,d,e] = sum_n k[d,n]*v[e,n] ----------------
__global__ void ctx_zero_k()
{
    int i = blockIdx.x * 256 + threadIdx.x;
    if (i < Bn * 4 * 256) g_ctx[i] = 0.f;
}

__global__ void ctx_k(const float* __restrict__ ks, const float* __restrict__ vs)
{
    // grid (16 = b*h, 8 = n split), block 256 = (d,e) pairs
    const int bh = blockIdx.x;
    const int b = bh >> 2, hd = bh & 3;
    const int d = threadIdx.x >> 4, e = threadIdx.x & 15;
    const float* kb = ks + ((size_t)b * Cd + hd * 16) * Nh;
    const float* vb = vs + ((size_t)b * Cd + hd * 16) * Nh;
    __shared__ __align__(16) float sk[16 * 260];
    __shared__ __align__(16) float sv[16 * 260];
    float acc = 0.f;
    const int n00 = blockIdx.y * 4096;
    for (int n0 = n00; n0 < n00 + 4096; n0 += 256) {
        __syncthreads();
        for (int t = threadIdx.x; t < 4096; t += 256) {
            int dd = t >> 8, nn = t & 255;
            sk[dd * 260 + nn] = kb[(size_t)dd * Nh + n0 + nn];
            sv[dd * 260 + nn] = vb[(size_t)dd * Nh + n0 + nn];
        }
        __syncthreads();
#pragma unroll 4
        for (int nn = 0; nn < 256; nn++)
            acc += sk[d * 260 + nn] * sv[e * 260 + nn];
    }
    atomicAdd(&g_ctx[(size_t)bh * 256 + d * 16 + e], acc);
}

// ---------------- att: dense (zeros at anchor), nonanchor = ctx^T @ q ----------------
__global__ void att_k(const float* __restrict__ qs, float* __restrict__ att)
{
    // grid (Nh/256, B*HEADS), block 256
    const int bh = blockIdx.y;
    const int b = bh >> 2, hd = bh & 3;
    __shared__ float sc[256];
    sc[threadIdx.x] = g_ctx[(size_t)bh * 256 + threadIdx.x];
    __syncthreads();
    const int n = blockIdx.x * 256 + threadIdx.x;
    const int i = n >> 7, jc = n & 127;
    float qv[16];
    const float* qb = qs + ((size_t)b * Cd + hd * 16) * Nh + n;
#pragma unroll
    for (int d = 0; d < 16; d++) qv[d] = qb[(size_t)d * Nh];
    const int sel_na = (i & 1);
    const int jf_na = 2 * jc + sel_na;
    const int jf_ac = 2 * jc + 1 - sel_na;
    float* ab = att + ((size_t)b * Cd + hd * 16) * HWC + (size_t)i * Ww;
#pragma unroll
    for (int e = 0; e < 16; e++) {
        float s = 0.f;
#pragma unroll
        for (int d = 0; d < 16; d++) s += sc[d * 16 + e] * qv[d];
        ab[(size_t)e * HWC + jf_na] = s;
        ab[(size_t)e * HWC + jf_ac] = 0.f;
    }
}

// ---------------- 5x5 conv 64->128, pad 2 (dominant compute) ----------------
// block 256 thr: 16x16 px tile x 16 oc. thread: 4 px (x-consecutive) x 4 oc.
// grid: (W/16, H/16, B*8)
__global__ void __launch_bounds__(256)
conv5x5_k(const float* __restrict__ in, const float* __restrict__ w,
          const float* __restrict__ bias, float* __restrict__ out)
{
    constexpr int TIN = 20;
    __shared__ __align__(16) float sIn[TIN * TIN];
    __shared__ __align__(16) float sW[25 * 16];   // [tap][oc_local]
    const int bz = blockIdx.z;
    const int b = bz >> 3, ocg = bz & 7;
    const int oq  = threadIdx.x >> 6;        // 0..3 (oc quad)
    const int t6  = threadIdx.x & 63;
    const int py  = t6 >> 2;                 // 0..15
    const int px4 = (t6 & 3) * 4;            // 0,4,8,12
    const int x0 = blockIdx.x * 16, y0 = blockIdx.y * 16;

    float acc[16];
#pragma unroll
    for (int o = 0; o < 4; o++) {
        float bv = __ldg(&bias[ocg * 16 + oq * 4 + o]);
#pragma unroll
        for (int l = 0; l < 4; l++) acc[o * 4 + l] = bv;
    }

    const float* inb = in + (size_t)b * Cd * HWC;
    for (int ci = 0; ci < Cd; ci++) {
        __syncthreads();
        for (int t = threadIdx.x; t < TIN * TIN; t += 256) {
            int yy = y0 + t / TIN - 2;
            int xx = x0 + t % TIN - 2;
            float v = 0.f;
            if (yy >= 0 && yy < Hh && xx >= 0 && xx < Ww)
                v = inb[(size_t)ci * HWC + yy * Ww + xx];
            sIn[t] = v;
        }
        for (int t = threadIdx.x; t < 400; t += 256) {
            int ol = t & 15, k = t >> 4;
            sW[k * 16 + ol] = w[((size_t)(ocg * 16 + ol) * Cd + ci) * 25 + k];
        }
        __syncthreads();
#pragma unroll
        for (int ky = 0; ky < 5; ky++) {
            const float* rowp = &sIn[(py + ky) * TIN + px4];
            float xv[8];
            *(float4*)&xv[0] = *(const float4*)rowp;
            *(float4*)&xv[4] = *(const float4*)(rowp + 4);
#pragma unroll
            for (int kx = 0; kx < 5; kx++) {
                float4 wv = *(const float4*)&sW[(ky * 5 + kx) * 16 + oq * 4];
#pragma unroll
                for (int l = 0; l < 4; l++) {
                    float x = xv[kx + l];
                    acc[0 * 4 + l] = fmaf(wv.x, x, acc[0 * 4 + l]);
                    acc[1 * 4 + l] = fmaf(wv.y, x, acc[1 * 4 + l]);
                    acc[2 * 4 + l] = fmaf(wv.z, x, acc[2 * 4 + l]);
                    acc[3 * 4 + l] = fmaf(wv.w, x, acc[3 * 4 + l]);
                }
            }
        }
    }

    float* ob = out + ((size_t)b * 128 + ocg * 16 + oq * 4) * HWC
                    + (size_t)(y0 + py) * Ww + x0 + px4;
#pragma unroll
    for (int o = 0; o < 4; o++) {
        float4 v = make_float4(acc[o * 4 + 0], acc[o * 4 + 1], acc[o * 4 + 2], acc[o * 4 + 3]);
        *(float4*)(ob + (size_t)o * HWC) = v;
    }
}

// ---------------- driver ----------------
extern "C" void kernel_launch(void* const* d_in, const int* in_sizes, int n_in,
                              void* d_out, int out_size)
{
    const float* x1  = (const float*)d_in[0];
    const float* x2  = (const float*)d_in[1];
    const float* q1w = (const float*)d_in[2],  *q1b = (const float*)d_in[3];
    const float* q2w = (const float*)d_in[4],  *q2b = (const float*)d_in[5];
    const float* k1w = (const float*)d_in[6],  *k1b = (const float*)d_in[7];
    const float* k2w = (const float*)d_in[8],  *k2b = (const float*)d_in[9];
    const float* v1w = (const float*)d_in[10], *v1b = (const float*)d_in[11];
    const float* v2w = (const float*)d_in[12], *v2b = (const float*)d_in[13];
    const float* rw  = (const float*)d_in[14], *rb  = (const float*)d_in[15];
    const float* m1w = (const float*)d_in[16], *m1b = (const float*)d_in[17];
    const float* m2w = (const float*)d_in[18], *m2b = (const float*)d_in[19];
    const float* m3w = (const float*)d_in[20], *m3b = (const float*)d_in[21];
    float* out = (float*)d_out;

    float *t, *qs, *ks, *vs, *att, *attn, *m1, *m2;
    cudaGetSymbolAddress((void**)&t,    g_t);
    cudaGetSymbolAddress((void**)&qs,   g_qs);
    cudaGetSymbolAddress((void**)&ks,   g_ks);
    cudaGetSymbolAddress((void**)&vs,   g_vs);
    cudaGetSymbolAddress((void**)&att,  g_att);
    cudaGetSymbolAddress((void**)&attn, g_attn);
    cudaGetSymbolAddress((void**)&m1,   g_m1);
    cudaGetSymbolAddress((void**)&m2,   g_m2);

    dim3 g1(HWC / 128, 1, Bn);

    // q/k/v paths: masked 1x1 conv -> depthwise 3x3 + squeeze
    conv1x1_k<64, 64, 0><<<g1, 128>>>(x1, q1w, q1b, nullptr, t, 2);          // nonanchor mask
    dw3x3_squeeze_k<<<dim3(Hh, Bn * Cd), Wh>>>(t, q2w, q2b, qs, 1);          // nonanchor squeeze
    conv1x1_k<64, 64, 0><<<g1, 128>>>(x1, k1w, k1b, nullptr, t, 1);          // anchor mask
    dw3x3_squeeze_k<<<dim3(Hh, Bn * Cd), Wh>>>(t, k2w, k2b, ks, 0);          // anchor squeeze
    conv1x1_k<64, 64, 0><<<g1, 128>>>(x2, v1w, v1b, nullptr, t, 0);          // no mask
    dw3x3_squeeze_k<<<dim3(Hh, Bn * Cd), Wh>>>(t, v2w, v2b, vs, 0);          // anchor squeeze

    // softmaxes (in place)
    softmax_rows_k<<<Bn * Cd, 256>>>(ks);
    softmax_q_k<<<(Bn * 4 * Nh) / 256, 256>>>(qs);

    // ctx then att (dense with checkerboard zeros)
    ctx_zero_k<<<16, 256>>>();
    ctx_k<<<dim3(Bn * 4, 8), 256>>>(ks, vs);
    att_k<<<dim3(Nh / 256, Bn * 4), 256>>>(qs, att);

    // attention = conv5x5(att)
    conv5x5_k<<<dim3(Ww / 16, Hh / 16, Bn * 8), 256>>>(att, rw, rb, attn);

    // MLP: m1 (gelu) -> dw3x3 (gelu) -> m3 (+ residual)
    conv1x1_k<128, 256, 1><<<dim3(HWC / 128, 4, Bn), 128>>>(attn, m1w, m1b, nullptr, m1, 0);
    dw3x3_gelu_k<<<dim3(Hh, Bn * 256), Ww>>>(m1, m2w, m2b, m2);
    conv1x1_k<256, 128, 2><<<dim3(HWC / 128, 2, Bn), 128>>>(m2, m3w, m3b, attn, out, 0);
}

// round 5
// speedup vs baseline: 1.5767x; 1.5767x over previous
#include <cuda_runtime.h>
#include <math.h>

constexpr int Bn = 4;
constexpr int Cd = 64;
constexpr int Hh = 256;
constexpr int Ww = 256;
constexpr int HWC = Hh * Ww;      // 65536
constexpr int Wh = 128;
constexpr int Nh = Hh * Wh;       // 32768

// ---------------- scratch (alloc-free: __device__ globals) ----------------
__device__ float g_t  [(size_t)Bn * Cd  * HWC];   //  67 MB  1x1-conv temp
__device__ float g_qs [(size_t)Bn * Cd  * Nh ];   //  33.5MB squeezed q
__device__ float g_ks [(size_t)Bn * Cd  * Nh ];   //  33.5MB squeezed k
__device__ float g_vs [(size_t)Bn * Cd  * Nh ];   //  33.5MB squeezed v
__device__ float g_ctx[Bn * 4 * 256];             //  16 KB  per (b,head) 16x16
__device__ float g_att[(size_t)Bn * Cd  * Nh ];   //  33.5MB SQUEEZED att
__device__ float g_attn[(size_t)Bn * 128 * HWC];  // 134 MB  attention (residual)
__device__ float g_m1 [(size_t)Bn * 256 * HWC];   // 268 MB
__device__ float g_m2 [(size_t)Bn * 256 * HWC];   // 268 MB

__device__ __forceinline__ float gelu_f(float x) {
    return 0.5f * x * (1.0f + erff(x * 0.7071067811865476f));
}

// ---------------- 1x1 conv v2: register-tiled GEMM ----------------
// block 256 thr. tile: 128 px x OCT oc. thread: 4 px x (OCT/8) oc.
// grid: (HW/128, OC/OCT, B). ACT: 0 none, 1 gelu, 2 +res
// maskmode: 0 none, 1 keep (i+j) odd, 2 keep (i+j) even (applied at staging)
template<int IC, int OC, int OCT, int ACT>
__global__ void __launch_bounds__(256)
conv1x1_v2_k(const float* __restrict__ in, const float* __restrict__ w,
             const float* __restrict__ bias, const float* __restrict__ res,
             float* __restrict__ out, int maskmode)
{
    constexpr int NO  = OCT / 8;      // oc per thread (8 or 16)
    constexpr int SWP = OCT + 4;      // padded sW row stride (floats)
    __shared__ __align__(16) float sX[16 * 128];
    __shared__ __align__(16) float sW[16 * SWP];

    const int b   = blockIdx.z;
    const int ocg = blockIdx.y;
    const int p0  = blockIdx.x * 128;
    const int pxb = (threadIdx.x & 31) * 4;
    const int ocb = (threadIdx.x >> 5) * NO;
    const int target = (maskmode == 1) ? 1 : 0;

    float acc[NO * 4];
#pragma unroll
    for (int i = 0; i < NO * 4; i++) acc[i] = 0.f;

    const float* inb = in + (size_t)b * IC * HWC + p0;
    const float* wb  = w + (size_t)(ocg * OCT) * IC;

    for (int cc = 0; cc < IC; cc += 16) {
        __syncthreads();
        // stage input [16 ci][128 px], with optional checkerboard mask
        for (int t = threadIdx.x; t < 512; t += 256) {
            int ci = t >> 5, v = t & 31;
            float4 x = *(const float4*)&inb[(size_t)(cc + ci) * HWC + v * 4];
            if (maskmode != 0) {
                int p = p0 + (v << 2);
                int par0 = ((p >> 8) + (p & 255)) & 1;   // parity of slot 0
                if (par0 == target) { x.y = 0.f; x.w = 0.f; }
                else                { x.x = 0.f; x.z = 0.f; }
            }
            *(float4*)&sX[ci * 128 + v * 4] = x;
        }
        // stage weights transposed: sW[ci][oc], loaded as float4 along IC
        for (int t = threadIdx.x; t < OCT * 4; t += 256) {
            int oc = t >> 2, u = t & 3;
            float4 wv = *(const float4*)&wb[(size_t)oc * IC + cc + u * 4];
            sW[(u * 4 + 0) * SWP + oc] = wv.x;
            sW[(u * 4 + 1) * SWP + oc] = wv.y;
            sW[(u * 4 + 2) * SWP + oc] = wv.z;
            sW[(u * 4 + 3) * SWP + oc] = wv.w;
        }
        __syncthreads();
#pragma unroll
        for (int ci = 0; ci < 16; ci++) {
            float4 xv = *(const float4*)&sX[ci * 128 + pxb];
            float xs[4] = {xv.x, xv.y, xv.z, xv.w};
#pragma unroll
            for (int o4 = 0; o4 < NO / 4; o4++) {
                float4 wv = *(const float4*)&sW[ci * SWP + ocb + o4 * 4];
#pragma unroll
                for (int l = 0; l < 4; l++) {
                    float x = xs[l];
                    acc[(o4 * 4 + 0) * 4 + l] = fmaf(wv.x, x, acc[(o4 * 4 + 0) * 4 + l]);
                    acc[(o4 * 4 + 1) * 4 + l] = fmaf(wv.y, x, acc[(o4 * 4 + 1) * 4 + l]);
                    acc[(o4 * 4 + 2) * 4 + l] = fmaf(wv.z, x, acc[(o4 * 4 + 2) * 4 + l]);
                    acc[(o4 * 4 + 3) * 4 + l] = fmaf(wv.w, x, acc[(o4 * 4 + 3) * 4 + l]);
                }
            }
        }
    }

    float* ob = out + ((size_t)b * OC + ocg * OCT + ocb) * HWC + p0 + pxb;
    const float* resb = (ACT == 2)
        ? (res + ((size_t)b * OC + ocg * OCT + ocb) * HWC + p0 + pxb) : nullptr;
#pragma unroll
    for (int o = 0; o < NO; o++) {
        float bv = __ldg(&bias[ocg * OCT + ocb + o]);
        float4 v = make_float4(acc[o * 4 + 0] + bv, acc[o * 4 + 1] + bv,
                               acc[o * 4 + 2] + bv, acc[o * 4 + 3] + bv);
        if (ACT == 1) {
            v.x = gelu_f(v.x); v.y = gelu_f(v.y); v.z = gelu_f(v.z); v.w = gelu_f(v.w);
        }
        if (ACT == 2) {
            float4 r = *(const float4*)&resb[(size_t)o * HWC];
            v.x += r.x; v.y += r.y; v.z += r.z; v.w += r.w;
        }
        *(float4*)&ob[(size_t)o * HWC] = v;
    }
}

// ---------------- depthwise 3x3 + checkerboard squeeze ----------------
__global__ void dw3x3_squeeze_k(const float* __restrict__ in, const float* __restrict__ w,
                                const float* __restrict__ bias, float* __restrict__ out, int type)
{
    const int i  = blockIdx.x;
    const int bc = blockIdx.y;
    const int c  = bc & 63;
    const int jc = threadIdx.x;
    const int sel = type ? (i & 1) : (1 - (i & 1));
    const int jf  = 2 * jc + sel;
    const float* inp = in + (size_t)bc * HWC;
    float acc = __ldg(&bias[c]);
#pragma unroll
    for (int dy = -1; dy <= 1; dy++) {
        int ii = i + dy;
        if (ii < 0 || ii >= Hh) continue;
#pragma unroll
        for (int dx = -1; dx <= 1; dx++) {
            int jj = jf + dx;
            if (jj < 0 || jj >= Ww) continue;
            acc += __ldg(&w[c * 9 + (dy + 1) * 3 + (dx + 1)]) * inp[ii * Ww + jj];
        }
    }
    out[(size_t)bc * Nh + i * Wh + jc] = acc;
}

// ---------------- depthwise 3x3 + gelu (m2) ----------------
__global__ void dw3x3_gelu_k(const float* __restrict__ in, const float* __restrict__ w,
                             const float* __restrict__ bias, float* __restrict__ out)
{
    const int i  = blockIdx.x;
    const int bc = blockIdx.y;
    const int c  = bc & 255;
    const int j  = threadIdx.x;
    const float* inp = in + (size_t)bc * HWC;
    float acc = __ldg(&bias[c]);
#pragma unroll
    for (int dy = -1; dy <= 1; dy++) {
        int ii = i + dy;
        if (ii < 0 || ii >= Hh) continue;
#pragma unroll
        for (int dx = -1; dx <= 1; dx++) {
            int jj = j + dx;
            if (jj < 0 || jj >= Ww) continue;
            acc += __ldg(&w[c * 9 + (dy + 1) * 3 + (dx + 1)]) * inp[ii * Ww + jj];
        }
    }
    out[(size_t)bc * HWC + i * Ww + j] = gelu_f(acc);
}

// ---------------- softmax over N=32768 per (b,c) row, in place ----------------
__global__ void softmax_rows_k(float* __restrict__ x)
{
    const size_t base = (size_t)blockIdx.x * Nh;
    __shared__ float red[256];
    float mx = -1e30f;
    for (int n = threadIdx.x; n < Nh; n += 256) mx = fmaxf(mx, x[base + n]);
    red[threadIdx.x] = mx; __syncthreads();
    for (int s = 128; s > 0; s >>= 1) {
        if (threadIdx.x < s) red[threadIdx.x] = fmaxf(red[threadIdx.x], red[threadIdx.x + s]);
        __syncthreads();
    }
    mx = red[0]; __syncthreads();
    float sum = 0.f;
    for (int n = threadIdx.x; n < Nh; n += 256) sum += __expf(x[base + n] - mx);
    red[threadIdx.x] = sum; __syncthreads();
    for (int s = 128; s > 0; s >>= 1) {
        if (threadIdx.x < s) red[threadIdx.x] += red[threadIdx.x + s];
        __syncthreads();
    }
    float inv = 1.0f / red[0];
    for (int n = threadIdx.x; n < Nh; n += 256) x[base + n] = __expf(x[base + n] - mx) * inv;
}

// ---------------- softmax over d=16 channels (q path), in place ----------------
__global__ void softmax_q_k(float* __restrict__ q)
{
    const size_t idx = (size_t)blockIdx.x * 256 + threadIdx.x;
    const int n  = (int)(idx & (Nh - 1));
    const int bh = (int)(idx >> 15);
    const int b = bh >> 2, hd = bh & 3;
    float* base = q + ((size_t)b * Cd + hd * 16) * Nh + n;
    float v[16]; float mx = -1e30f;
#pragma unroll
    for (int d = 0; d < 16; d++) { v[d] = base[(size_t)d * Nh]; mx = fmaxf(mx, v[d]); }
    float s = 0.f;
#pragma unroll
    for (int d = 0; d < 16; d++) { v[d] = __expf(v[d] - mx); s += v[d]; }
    float inv = 1.0f / s;
#pragma unroll
    for (int d = 0; d < 16; d++) base[(size_t)d * Nh] = v[d] * inv;
}

// ---------------- ctx[b,h,d,e] = sum_n k[d,n]*v[e,n] ----------------
__global__ void ctx_zero_k()
{
    int i = blockIdx.x * 256 + threadIdx.x;
    if (i < Bn * 4 * 256) g_ctx[i] = 0.f;
}

__global__ void ctx_k(const float* __restrict__ ks, const float* __restrict__ vs)
{
    const int bh = blockIdx.x;
    const int b = bh >> 2, hd = bh & 3;
    const int d = threadIdx.x >> 4, e = threadIdx.x & 15;
    const float* kb = ks + ((size_t)b * Cd + hd * 16) * Nh;
    const float* vb = vs + ((size_t)b * Cd + hd * 16) * Nh;
    __shared__ __align__(16) float sk[16 * 260];
    __shared__ __align__(16) float sv[16 * 260];
    float acc = 0.f;
    const int n00 = blockIdx.y * 4096;
    for (int n0 = n00; n0 < n00 + 4096; n0 += 256) {
        __syncthreads();
        for (int t = threadIdx.x; t < 4096; t += 256) {
            int dd = t >> 8, nn = t & 255;
            sk[dd * 260 + nn] = kb[(size_t)dd * Nh + n0 + nn];
            sv[dd * 260 + nn] = vb[(size_t)dd * Nh + n0 + nn];
        }
        __syncthreads();
#pragma unroll 4
        for (int nn = 0; nn < 256; nn++)
            acc += sk[d * 260 + nn] * sv[e * 260 + nn];
    }
    atomicAdd(&g_ctx[(size_t)bh * 256 + d * 16 + e], acc);
}

// ---------------- att (SQUEEZED): att_sq[c][i][jc] = ctx^T @ q ----------------
__global__ void att_k(const float* __restrict__ qs, float* __restrict__ att_sq)
{
    const int bh = blockIdx.y;
    const int b = bh >> 2, hd = bh & 3;
    __shared__ float sc[256];
    sc[threadIdx.x] = g_ctx[(size_t)bh * 256 + threadIdx.x];
    __syncthreads();
    const int n = blockIdx.x * 256 + threadIdx.x;
    float qv[16];
    const float* qb = qs + ((size_t)b * Cd + hd * 16) * Nh + n;
#pragma unroll
    for (int d = 0; d < 16; d++) qv[d] = qb[(size_t)d * Nh];
    float* ab = att_sq + ((size_t)b * Cd + hd * 16) * Nh + n;
#pragma unroll
    for (int e = 0; e < 16; e++) {
        float s = 0.f;
#pragma unroll
        for (int d = 0; d < 16; d++) s += sc[d * 16 + e] * qv[d];
        ab[(size_t)e * Nh] = s;
    }
}

// ---------------- SPARSE 5x5 conv 64->128 on checkerboard input ----------------
// Input att_sq: squeezed nonanchor values; dense att(i,j)=att_sq[i][jc] at
// j = 2*jc + (i&1), zero elsewhere. Output pixel (y,x) of class q=(y+x)&1 uses
// only taps with (dy+dx) parity == q: 13 (q=0) or 12 (q=1) of 25 taps.
// block 256 = 8 warps: warp = (oq 0..3) x (qc 0..1). warp lane: py=lane>>1 (row),
// m=(lane&1)*4 (px group). Thread: 4 px (x stride 2, same class) x 4 oc.
// grid: (W/16, H/16, B*8)
__global__ void __launch_bounds__(256)
conv5x5_sp_k(const float* __restrict__ in, const float* __restrict__ w,
             const float* __restrict__ bias, float* __restrict__ out)
{
    constexpr int CK = 4;
    __shared__ __align__(16) float sSq[CK * 240];   // per ci: 20 rows x 12 (10 used)
    __shared__ __align__(16) float sW[CK * 400];    // per ci: [tap][oc_local]
    const int bz = blockIdx.z;
    const int b = bz >> 3, ocg = bz & 7;
    const int wid  = threadIdx.x >> 5;
    const int oq   = wid >> 1;
    const int qc   = wid & 1;
    const int lane = threadIdx.x & 31;
    const int py   = lane >> 1;
    const int m    = (lane & 1) * 4;
    const int x0 = blockIdx.x * 16, y0 = blockIdx.y * 16;
    const int p  = qc ^ (py & 1);      // x parity of this thread's pixels

    float acc[16];
#pragma unroll
    for (int o = 0; o < 4; o++) {
        float bv = __ldg(&bias[ocg * 16 + oq * 4 + o]);
#pragma unroll
        for (int l = 0; l < 4; l++) acc[o * 4 + l] = bv;
    }

    const float* inb = in + (size_t)b * Cd * Nh;
    for (int cc = 0; cc < Cd; cc += CK) {
        __syncthreads();
#pragma unroll
        for (int c4 = 0; c4 < CK; c4++) {
            const int ci = cc + c4;
            for (int t = threadIdx.x; t < 200; t += 256) {
                int r = t / 10, s = t - r * 10;
                int ii = y0 - 2 + r;
                int jc = (x0 >> 1) - 1 + s;
                float v = 0.f;
                if (ii >= 0 && ii < Hh && jc >= 0 && jc < Wh)
                    v = inb[(size_t)ci * Nh + ii * Wh + jc];
                sSq[c4 * 240 + r * 12 + s] = v;
            }
            for (int t = threadIdx.x; t < 400; t += 256) {
                int ol = t & 15, k = t >> 4;
                sW[c4 * 400 + k * 16 + ol] = w[((size_t)(ocg * 16 + ol) * Cd + ci) * 25 + k];
            }
        }
        __syncthreads();
#pragma unroll
        for (int c4 = 0; c4 < CK; c4++) {
            const float* tile = &sSq[c4 * 240];
            const float* wt   = &sW[c4 * 400];
#pragma unroll
            for (int ky = 0; ky < 5; ky++) {
                const float* row = &tile[(py + ky) * 12 + m];
                if (((ky + qc) & 1) == 0) {
                    // kx in {0,2,4}: s = m + l + kx/2
                    float xv[6];
                    float4 a = *(const float4*)row;
                    xv[0] = a.x; xv[1] = a.y; xv[2] = a.z; xv[3] = a.w;
                    xv[4] = row[4]; xv[5] = row[5];
#pragma unroll
                    for (int kxh = 0; kxh < 3; kxh++) {
                        float4 wv = *(const float4*)&wt[(ky * 5 + 2 * kxh) * 16 + oq * 4];
#pragma unroll
                        for (int l = 0; l < 4; l++) {
                            float x = xv[l + kxh];
                            acc[0 * 4 + l] = fmaf(wv.x, x, acc[0 * 4 + l]);
                            acc[1 * 4 + l] = fmaf(wv.y, x, acc[1 * 4 + l]);
                            acc[2 * 4 + l] = fmaf(wv.z, x, acc[2 * 4 + l]);
                            acc[3 * 4 + l] = fmaf(wv.w, x, acc[3 * 4 + l]);
                        }
                    }
                } else {
                    // kx in {1,3}: s = m + l + (kx-1)/2 + p
                    float xv[5];
                    const float* rowp = row + p;
#pragma unroll
                    for (int j = 0; j < 5; j++) xv[j] = rowp[j];
#pragma unroll
                    for (int kxh = 0; kxh < 2; kxh++) {
                        float4 wv = *(const float4*)&wt[(ky * 5 + 2 * kxh + 1) * 16 + oq * 4];
#pragma unroll
                        for (int l = 0; l < 4; l++) {
                            float x = xv[l + kxh];
                            acc[0 * 4 + l] = fmaf(wv.x, x, acc[0 * 4 + l]);
                            acc[1 * 4 + l] = fmaf(wv.y, x, acc[1 * 4 + l]);
                            acc[2 * 4 + l] = fmaf(wv.z, x, acc[2 * 4 + l]);
                            acc[3 * 4 + l] = fmaf(wv.w, x, acc[3 * 4 + l]);
                        }
                    }
                }
            }
        }
    }

    // write 4 oc x 4 px (x = x0 + p + 2*(m+l))
    float* ob = out + ((size_t)b * 128 + ocg * 16 + oq * 4) * HWC
                    + (size_t)(y0 + py) * Ww + x0 + p + 2 * m;
#pragma unroll
    for (int o = 0; o < 4; o++)
#pragma unroll
        for (int l = 0; l < 4; l++)
            ob[(size_t)o * HWC + 2 * l] = acc[o * 4 + l];
}

// ---------------- driver ----------------
extern "C" void kernel_launch(void* const* d_in, const int* in_sizes, int n_in,
                              void* d_out, int out_size)
{
    const float* x1  = (const float*)d_in[0];
    const float* x2  = (const float*)d_in[1];
    const float* q1w = (const float*)d_in[2],  *q1b = (const float*)d_in[3];
    const float* q2w = (const float*)d_in[4],  *q2b = (const float*)d_in[5];
    const float* k1w = (const float*)d_in[6],  *k1b = (const float*)d_in[7];
    const float* k2w = (const float*)d_in[8],  *k2b = (const float*)d_in[9];
    const float* v1w = (const float*)d_in[10], *v1b = (const float*)d_in[11];
    const float* v2w = (const float*)d_in[12], *v2b = (const float*)d_in[13];
    const float* rw  = (const float*)d_in[14], *rb  = (const float*)d_in[15];
    const float* m1w = (const float*)d_in[16], *m1b = (const float*)d_in[17];
    const float* m2w = (const float*)d_in[18], *m2b = (const float*)d_in[19];
    const float* m3w = (const float*)d_in[20], *m3b = (const float*)d_in[21];
    float* out = (float*)d_out;

    float *t, *qs, *ks, *vs, *att, *attn, *m1, *m2;
    cudaGetSymbolAddress((void**)&t,    g_t);
    cudaGetSymbolAddress((void**)&qs,   g_qs);
    cudaGetSymbolAddress((void**)&ks,   g_ks);
    cudaGetSymbolAddress((void**)&vs,   g_vs);
    cudaGetSymbolAddress((void**)&att,  g_att);
    cudaGetSymbolAddress((void**)&attn, g_attn);
    cudaGetSymbolAddress((void**)&m1,   g_m1);
    cudaGetSymbolAddress((void**)&m2,   g_m2);

    dim3 g1(HWC / 128, 1, Bn);

    // q/k/v paths: masked 1x1 conv -> depthwise 3x3 + squeeze
    conv1x1_v2_k<64, 64, 64, 0><<<g1, 256>>>(x1, q1w, q1b, nullptr, t, 2);   // nonanchor mask
    dw3x3_squeeze_k<<<dim3(Hh, Bn * Cd), Wh>>>(t, q2w, q2b, qs, 1);          // nonanchor squeeze
    conv1x1_v2_k<64, 64, 64, 0><<<g1, 256>>>(x1, k1w, k1b, nullptr, t, 1);   // anchor mask
    dw3x3_squeeze_k<<<dim3(Hh, Bn * Cd), Wh>>>(t, k2w, k2b, ks, 0);          // anchor squeeze
    conv1x1_v2_k<64, 64, 64, 0><<<g1, 256>>>(x2, v1w, v1b, nullptr, t, 0);   // no mask
    dw3x3_squeeze_k<<<dim3(Hh, Bn * Cd), Wh>>>(t, v2w, v2b, vs, 0);          // anchor squeeze

    // softmaxes (in place)
    softmax_rows_k<<<Bn * Cd, 256>>>(ks);
    softmax_q_k<<<(Bn * 4 * Nh) / 256, 256>>>(qs);

    // ctx then squeezed att
    ctx_zero_k<<<16, 256>>>();
    ctx_k<<<dim3(Bn * 4, 8), 256>>>(ks, vs);
    att_k<<<dim3(Nh / 256, Bn * 4), 256>>>(qs, att);

    // attention = sparse conv5x5(att)
    conv5x5_sp_k<<<dim3(Ww / 16, Hh / 16, Bn * 8), 256>>>(att, rw, rb, attn);

    // MLP: m1 (gelu) -> dw3x3 (gelu) -> m3 (+ residual)
    conv1x1_v2_k<128, 256, 128, 1><<<dim3(HWC / 128, 2, Bn), 256>>>(attn, m1w, m1b, nullptr, m1, 0);
    dw3x3_gelu_k<<<dim3(Hh, Bn * 256), Ww>>>(m1, m2w, m2b, m2);
    conv1x1_v2_k<256, 128, 128, 2><<<dim3(HWC / 128, 1, Bn), 256>>>(m2, m3w, m3b, attn, out, 0);
}

// round 6
// speedup vs baseline: 1.6501x; 1.0466x over previous
#include <cuda_runtime.h>
#include <math.h>

constexpr int Bn = 4;
constexpr int Cd = 64;
constexpr int Hh = 256;
constexpr int Ww = 256;
constexpr int HWC = Hh * Ww;      // 65536
constexpr int Wh = 128;
constexpr int Nh = Hh * Wh;       // 32768

typedef unsigned long long ull;

// ---------------- scratch (alloc-free: __device__ globals) ----------------
__device__ float g_t  [(size_t)Bn * Cd  * HWC];   //  67 MB  1x1-conv temp
__device__ float g_qs [(size_t)Bn * Cd  * Nh ];   //  33.5MB squeezed q (raw)
__device__ float g_ks [(size_t)Bn * Cd  * Nh ];   //  33.5MB squeezed k
__device__ float g_vs [(size_t)Bn * Cd  * Nh ];   //  33.5MB squeezed v
__device__ float g_ctxp[Bn * 4 * 8 * 256];        // 128 KB  partial ctx
__device__ float g_att[(size_t)Bn * Cd  * Nh ];   //  33.5MB SQUEEZED att
__device__ float g_attn[(size_t)Bn * 128 * HWC];  // 134 MB  attention (residual)
__device__ float g_m1 [(size_t)Bn * 256 * HWC];   // 268 MB
__device__ float g_m2 [(size_t)Bn * 256 * HWC];   // 268 MB

__device__ __forceinline__ float gelu_f(float x) {
    return 0.5f * x * (1.0f + erff(x * 0.7071067811865476f));
}

// -------- packed fp32x2 helpers (Blackwell FFMA2: 2x fp32, exact) --------
__device__ __forceinline__ ull bcast2(float x) {
    ull d; asm("mov.b64 %0, {%1, %1};" : "=l"(d) : "f"(x)); return d;
}
__device__ __forceinline__ ull pack2(float lo, float hi) {
    ull d; asm("mov.b64 %0, {%1, %2};" : "=l"(d) : "f"(lo), "f"(hi)); return d;
}
__device__ __forceinline__ void unpack2(float& lo, float& hi, ull d) {
    asm("mov.b64 {%0, %1}, %2;" : "=f"(lo), "=f"(hi) : "l"(d));
}
__device__ __forceinline__ void fma2(ull& d, ull a, ull b) {
    asm("fma.rn.f32x2 %0, %1, %2, %0;" : "+l"(d) : "l"(a), "l"(b));
}

// ---------------- 1x1 conv v3: register-tiled GEMM, fp32x2 ----------------
// block 256 thr. tile: 128 px x OCT oc. thread: 4 px x (OCT/8) oc (paired).
// grid: (HW/128, OC/OCT, B). ACT: 0 none, 1 gelu, 2 +res
// maskmode: 0 none, 1 keep (i+j) odd, 2 keep (i+j) even (applied at staging)
template<int IC, int OC, int OCT, int ACT>
__global__ void __launch_bounds__(256)
conv1x1_v2_k(const float* __restrict__ in, const float* __restrict__ w,
             const float* __restrict__ bias, const float* __restrict__ res,
             float* __restrict__ out, int maskmode)
{
    constexpr int NO  = OCT / 8;      // oc per thread (8 or 16)
    constexpr int NP  = NO / 2;       // oc-pairs per thread
    constexpr int SWP = OCT + 4;      // padded sW row stride (floats)
    __shared__ __align__(16) float sX[16 * 128];
    __shared__ __align__(16) float sW[16 * SWP];

    const int b   = blockIdx.z;
    const int ocg = blockIdx.y;
    const int p0  = blockIdx.x * 128;
    const int pxb = (threadIdx.x & 31) * 4;
    const int ocb = (threadIdx.x >> 5) * NO;
    const int target = (maskmode == 1) ? 1 : 0;

    ull acc[NP * 4];
#pragma unroll
    for (int i = 0; i < NP * 4; i++) acc[i] = 0ULL;

    const float* inb = in + (size_t)b * IC * HWC + p0;
    const float* wb  = w + (size_t)(ocg * OCT) * IC;

    for (int cc = 0; cc < IC; cc += 16) {
        __syncthreads();
        // stage input [16 ci][128 px], with optional checkerboard mask
        for (int t = threadIdx.x; t < 512; t += 256) {
            int ci = t >> 5, v = t & 31;
            float4 x = *(const float4*)&inb[(size_t)(cc + ci) * HWC + v * 4];
            if (maskmode != 0) {
                int p = p0 + (v << 2);
                int par0 = ((p >> 8) + (p & 255)) & 1;
                if (par0 == target) { x.y = 0.f; x.w = 0.f; }
                else                { x.x = 0.f; x.z = 0.f; }
            }
            *(float4*)&sX[ci * 128 + v * 4] = x;
        }
        // stage weights transposed: sW[ci][oc]
        for (int t = threadIdx.x; t < OCT * 4; t += 256) {
            int oc = t >> 2, u = t & 3;
            float4 wv = *(const float4*)&wb[(size_t)oc * IC + cc + u * 4];
            sW[(u * 4 + 0) * SWP + oc] = wv.x;
            sW[(u * 4 + 1) * SWP + oc] = wv.y;
            sW[(u * 4 + 2) * SWP + oc] = wv.z;
            sW[(u * 4 + 3) * SWP + oc] = wv.w;
        }
        __syncthreads();
#pragma unroll
        for (int ci = 0; ci < 16; ci++) {
            float4 xv = *(const float4*)&sX[ci * 128 + pxb];
            ull xx[4];
            xx[0] = bcast2(xv.x); xx[1] = bcast2(xv.y);
            xx[2] = bcast2(xv.z); xx[3] = bcast2(xv.w);
#pragma unroll
            for (int o4 = 0; o4 < NO / 4; o4++) {
                ulonglong2 wv = *(const ulonglong2*)&sW[ci * SWP + ocb + o4 * 4];
#pragma unroll
                for (int l = 0; l < 4; l++) {
                    fma2(acc[(o4 * 2 + 0) * 4 + l], wv.x, xx[l]);
                    fma2(acc[(o4 * 2 + 1) * 4 + l], wv.y, xx[l]);
                }
            }
        }
    }

    float* ob = out + ((size_t)b * OC + ocg * OCT + ocb) * HWC + p0 + pxb;
    const float* resb = (ACT == 2)
        ? (res + ((size_t)b * OC + ocg * OCT + ocb) * HWC + p0 + pxb) : nullptr;
#pragma unroll
    for (int op = 0; op < NP; op++) {
        float fl[4], fh[4];
#pragma unroll
        for (int l = 0; l < 4; l++) unpack2(fl[l], fh[l], acc[op * 4 + l]);
        const int o0 = 2 * op, o1 = 2 * op + 1;
        float b0 = __ldg(&bias[ocg * OCT + ocb + o0]);
        float b1 = __ldg(&bias[ocg * OCT + ocb + o1]);
        float4 v0 = make_float4(fl[0] + b0, fl[1] + b0, fl[2] + b0, fl[3] + b0);
        float4 v1 = make_float4(fh[0] + b1, fh[1] + b1, fh[2] + b1, fh[3] + b1);
        if (ACT == 1) {
            v0.x = gelu_f(v0.x); v0.y = gelu_f(v0.y); v0.z = gelu_f(v0.z); v0.w = gelu_f(v0.w);
            v1.x = gelu_f(v1.x); v1.y = gelu_f(v1.y); v1.z = gelu_f(v1.z); v1.w = gelu_f(v1.w);
        }
        if (ACT == 2) {
            float4 r0 = *(const float4*)&resb[(size_t)o0 * HWC];
            float4 r1 = *(const float4*)&resb[(size_t)o1 * HWC];
            v0.x += r0.x; v0.y += r0.y; v0.z += r0.z; v0.w += r0.w;
            v1.x += r1.x; v1.y += r1.y; v1.z += r1.z; v1.w += r1.w;
        }
        *(float4*)&ob[(size_t)o0 * HWC] = v0;
        *(float4*)&ob[(size_t)o1 * HWC] = v1;
    }
}

// ---------------- depthwise 3x3 + checkerboard squeeze ----------------
__global__ void dw3x3_squeeze_k(const float* __restrict__ in, const float* __restrict__ w,
                                const float* __restrict__ bias, float* __restrict__ out, int type)
{
    const int i  = blockIdx.x;
    const int bc = blockIdx.y;
    const int c  = bc & 63;
    const int jc = threadIdx.x;
    const int sel = type ? (i & 1) : (1 - (i & 1));
    const int jf  = 2 * jc + sel;
    const float* inp = in + (size_t)bc * HWC;
    float acc = __ldg(&bias[c]);
#pragma unroll
    for (int dy = -1; dy <= 1; dy++) {
        int ii = i + dy;
        if (ii < 0 || ii >= Hh) continue;
#pragma unroll
        for (int dx = -1; dx <= 1; dx++) {
            int jj = jf + dx;
            if (jj < 0 || jj >= Ww) continue;
            acc += __ldg(&w[c * 9 + (dy + 1) * 3 + (dx + 1)]) * inp[ii * Ww + jj];
        }
    }
    out[(size_t)bc * Nh + i * Wh + jc] = acc;
}

// ---------------- depthwise 3x3 + gelu (m2) ----------------
__global__ void dw3x3_gelu_k(const float* __restrict__ in, const float* __restrict__ w,
                             const float* __restrict__ bias, float* __restrict__ out)
{
    const int i  = blockIdx.x;
    const int bc = blockIdx.y;
    const int c  = bc & 255;
    const int j  = threadIdx.x;
    const float* inp = in + (size_t)bc * HWC;
    float acc = __ldg(&bias[c]);
#pragma unroll
    for (int dy = -1; dy <= 1; dy++) {
        int ii = i + dy;
        if (ii < 0 || ii >= Hh) continue;
#pragma unroll
        for (int dx = -1; dx <= 1; dx++) {
            int jj = j + dx;
            if (jj < 0 || jj >= Ww) continue;
            acc += __ldg(&w[c * 9 + (dy + 1) * 3 + (dx + 1)]) * inp[ii * Ww + jj];
        }
    }
    out[(size_t)bc * HWC + i * Ww + j] = gelu_f(acc);
}

// ---------------- softmax over N=32768 per (b,c) row, in place ----------------
__global__ void softmax_rows_k(float* __restrict__ x)
{
    const size_t base = (size_t)blockIdx.x * Nh;
    __shared__ float red[256];
    float mx = -1e30f;
    for (int n = threadIdx.x; n < Nh; n += 256) mx = fmaxf(mx, x[base + n]);
    red[threadIdx.x] = mx; __syncthreads();
    for (int s = 128; s > 0; s >>= 1) {
        if (threadIdx.x < s) red[threadIdx.x] = fmaxf(red[threadIdx.x], red[threadIdx.x + s]);
        __syncthreads();
    }
    mx = red[0]; __syncthreads();
    float sum = 0.f;
    for (int n = threadIdx.x; n < Nh; n += 256) sum += __expf(x[base + n] - mx);
    red[threadIdx.x] = sum; __syncthreads();
    for (int s = 128; s > 0; s >>= 1) {
        if (threadIdx.x < s) red[threadIdx.x] += red[threadIdx.x + s];
        __syncthreads();
    }
    float inv = 1.0f / red[0];
    for (int n = threadIdx.x; n < Nh; n += 256) x[base + n] = __expf(x[base + n] - mx) * inv;
}

// ---------------- ctx partials: g_ctxp[bh][split][d*16+e] ----------------
__global__ void ctx_k(const float* __restrict__ ks, const float* __restrict__ vs)
{
    const int bh = blockIdx.x;
    const int b = bh >> 2, hd = bh & 3;
    const int d = threadIdx.x >> 4, e = threadIdx.x & 15;
    const float* kb = ks + ((size_t)b * Cd + hd * 16) * Nh;
    const float* vb = vs + ((size_t)b * Cd + hd * 16) * Nh;
    __shared__ __align__(16) float sk[16 * 260];
    __shared__ __align__(16) float sv[16 * 260];
    float acc = 0.f;
    const int n00 = blockIdx.y * 4096;
    for (int n0 = n00; n0 < n00 + 4096; n0 += 256) {
        __syncthreads();
        for (int t = threadIdx.x; t < 4096; t += 256) {
            int dd = t >> 8, nn = t & 255;
            sk[dd * 260 + nn] = kb[(size_t)dd * Nh + n0 + nn];
            sv[dd * 260 + nn] = vb[(size_t)dd * Nh + n0 + nn];
        }
        __syncthreads();
#pragma unroll 4
        for (int nn = 0; nn < 256; nn++)
            acc += sk[d * 260 + nn] * sv[e * 260 + nn];
    }
    g_ctxp[((size_t)bh * 8 + blockIdx.y) * 256 + d * 16 + e] = acc;
}

// ---------------- att (SQUEEZED) with fused q-softmax ----------------
__global__ void att_k(const float* __restrict__ qs, float* __restrict__ att_sq)
{
    const int bh = blockIdx.y;
    const int b = bh >> 2, hd = bh & 3;
    __shared__ float sc[256];
    {
        float s = 0.f;
#pragma unroll
        for (int sp = 0; sp < 8; sp++)
            s += g_ctxp[((size_t)bh * 8 + sp) * 256 + threadIdx.x];
        sc[threadIdx.x] = s;
    }
    __syncthreads();
    const int n = blockIdx.x * 256 + threadIdx.x;
    float qv[16];
    const float* qb = qs + ((size_t)b * Cd + hd * 16) * Nh + n;
    float mx = -1e30f;
#pragma unroll
    for (int d = 0; d < 16; d++) { qv[d] = qb[(size_t)d * Nh]; mx = fmaxf(mx, qv[d]); }
    float ssum = 0.f;
#pragma unroll
    for (int d = 0; d < 16; d++) { qv[d] = __expf(qv[d] - mx); ssum += qv[d]; }
    float inv = 1.0f / ssum;
#pragma unroll
    for (int d = 0; d < 16; d++) qv[d] *= inv;
    float* ab = att_sq + ((size_t)b * Cd + hd * 16) * Nh + n;
#pragma unroll
    for (int e = 0; e < 16; e++) {
        float s = 0.f;
#pragma unroll
        for (int d = 0; d < 16; d++) s += sc[d * 16 + e] * qv[d];
        ab[(size_t)e * Nh] = s;
    }
}

// ---------------- SPARSE 5x5 conv 64->128 on checkerboard input, fp32x2 ----------------
// block 256 = 8 warps: warp = (oq 0..3) x (qc 0..1). lane: py=lane>>1, m=(lane&1)*4.
// thread: 4 px (x stride 2, same class) x 4 oc (2 packed pairs).
// grid: (W/16, H/16, B*8)
__global__ void __launch_bounds__(256)
conv5x5_sp_k(const float* __restrict__ in, const float* __restrict__ w,
             const float* __restrict__ bias, float* __restrict__ out)
{
    constexpr int CK = 4;
    __shared__ __align__(16) float sSq[CK * 240];   // per ci: 20 rows x 12 (10 used)
    __shared__ __align__(16) float sW[CK * 400];    // per ci: [tap][oc_local]
    const int bz = blockIdx.z;
    const int b = bz >> 3, ocg = bz & 7;
    const int wid  = threadIdx.x >> 5;
    const int oq   = wid >> 1;
    const int qc   = wid & 1;
    const int lane = threadIdx.x & 31;
    const int py   = lane >> 1;
    const int m    = (lane & 1) * 4;
    const int x0 = blockIdx.x * 16, y0 = blockIdx.y * 16;
    const int p  = qc ^ (py & 1);      // x parity of this thread's pixels

    // acc[pair][l]: pair 0 = oc {0,1}, pair 1 = oc {2,3} of this oq quad
    ull acc[8];
    {
        float b0 = __ldg(&bias[ocg * 16 + oq * 4 + 0]);
        float b1 = __ldg(&bias[ocg * 16 + oq * 4 + 1]);
        float b2 = __ldg(&bias[ocg * 16 + oq * 4 + 2]);
        float b3 = __ldg(&bias[ocg * 16 + oq * 4 + 3]);
        ull p01 = pack2(b0, b1), p23 = pack2(b2, b3);
#pragma unroll
        for (int l = 0; l < 4; l++) { acc[l] = p01; acc[4 + l] = p23; }
    }

    const float* inb = in + (size_t)b * Cd * Nh;
    for (int cc = 0; cc < Cd; cc += CK) {
        __syncthreads();
#pragma unroll
        for (int c4 = 0; c4 < CK; c4++) {
            const int ci = cc + c4;
            for (int t = threadIdx.x; t < 200; t += 256) {
                int r = t / 10, s = t - r * 10;
                int ii = y0 - 2 + r;
                int jc = (x0 >> 1) - 1 + s;
                float v = 0.f;
                if (ii >= 0 && ii < Hh && jc >= 0 && jc < Wh)
                    v = inb[(size_t)ci * Nh + ii * Wh + jc];
                sSq[c4 * 240 + r * 12 + s] = v;
            }
            for (int t = threadIdx.x; t < 400; t += 256) {
                int ol = t & 15, k = t >> 4;
                sW[c4 * 400 + k * 16 + ol] = w[((size_t)(ocg * 16 + ol) * Cd + ci) * 25 + k];
            }
        }
        __syncthreads();
#pragma unroll
        for (int c4 = 0; c4 < CK; c4++) {
            const float* tile = &sSq[c4 * 240];
            const float* wt   = &sW[c4 * 400];
#pragma unroll
            for (int ky = 0; ky < 5; ky++) {
                const float* row = &tile[(py + ky) * 12 + m];
                if (((ky + qc) & 1) == 0) {
                    // kx in {0,2,4}
                    float4 a = *(const float4*)row;
                    ull xx[6];
                    xx[0] = bcast2(a.x); xx[1] = bcast2(a.y);
                    xx[2] = bcast2(a.z); xx[3] = bcast2(a.w);
                    xx[4] = bcast2(row[4]); xx[5] = bcast2(row[5]);
#pragma unroll
                    for (int kxh = 0; kxh < 3; kxh++) {
                        ulonglong2 wv = *(const ulonglong2*)&wt[(ky * 5 + 2 * kxh) * 16 + oq * 4];
#pragma unroll
                        for (int l = 0; l < 4; l++) {
                            fma2(acc[l],     wv.x, xx[l + kxh]);
                            fma2(acc[4 + l], wv.y, xx[l + kxh]);
                        }
                    }
                } else {
                    // kx in {1,3}
                    const float* rowp = row + p;
                    ull xx[5];
#pragma unroll
                    for (int j = 0; j < 5; j++) xx[j] = bcast2(rowp[j]);
#pragma unroll
                    for (int kxh = 0; kxh < 2; kxh++) {
                        ulonglong2 wv = *(const ulonglong2*)&wt[(ky * 5 + 2 * kxh + 1) * 16 + oq * 4];
#pragma unroll
                        for (int l = 0; l < 4; l++) {
                            fma2(acc[l],     wv.x, xx[l + kxh]);
                            fma2(acc[4 + l], wv.y, xx[l + kxh]);
                        }
                    }
                }
            }
        }
    }

    // write 4 oc x 4 px (x = x0 + p + 2*(m+l))
    float* ob = out + ((size_t)b * 128 + ocg * 16 + oq * 4) * HWC
                    + (size_t)(y0 + py) * Ww + x0 + p + 2 * m;
#pragma unroll
    for (int l = 0; l < 4; l++) {
        float v0, v1, v2, v3;
        unpack2(v0, v1, acc[l]);
        unpack2(v2, v3, acc[4 + l]);
        ob[0 * (size_t)HWC + 2 * l] = v0;
        ob[1 * (size_t)HWC + 2 * l] = v1;
        ob[2 * (size_t)HWC + 2 * l] = v2;
        ob[3 * (size_t)HWC + 2 * l] = v3;
    }
}

// ---------------- driver ----------------
extern "C" void kernel_launch(void* const* d_in, const int* in_sizes, int n_in,
                              void* d_out, int out_size)
{
    const float* x1  = (const float*)d_in[0];
    const float* x2  = (const float*)d_in[1];
    const float* q1w = (const float*)d_in[2],  *q1b = (const float*)d_in[3];
    const float* q2w = (const float*)d_in[4],  *q2b = (const float*)d_in[5];
    const float* k1w = (const float*)d_in[6],  *k1b = (const float*)d_in[7];
    const float* k2w = (const float*)d_in[8],  *k2b = (const float*)d_in[9];
    const float* v1w = (const float*)d_in[10], *v1b = (const float*)d_in[11];
    const float* v2w = (const float*)d_in[12], *v2b = (const float*)d_in[13];
    const float* rw  = (const float*)d_in[14], *rb  = (const float*)d_in[15];
    const float* m1w = (const float*)d_in[16], *m1b = (const float*)d_in[17];
    const float* m2w = (const float*)d_in[18], *m2b = (const float*)d_in[19];
    const float* m3w = (const float*)d_in[20], *m3b = (const float*)d_in[21];
    float* out = (float*)d_out;

    float *t, *qs, *ks, *vs, *att, *attn, *m1, *m2;
    cudaGetSymbolAddress((void**)&t,    g_t);
    cudaGetSymbolAddress((void**)&qs,   g_qs);
    cudaGetSymbolAddress((void**)&ks,   g_ks);
    cudaGetSymbolAddress((void**)&vs,   g_vs);
    cudaGetSymbolAddress((void**)&att,  g_att);
    cudaGetSymbolAddress((void**)&attn, g_attn);
    cudaGetSymbolAddress((void**)&m1,   g_m1);
    cudaGetSymbolAddress((void**)&m2,   g_m2);

    dim3 g1(HWC / 128, 1, Bn);

    // q/k/v paths: masked 1x1 conv -> depthwise 3x3 + squeeze
    conv1x1_v2_k<64, 64, 64, 0><<<g1, 256>>>(x1, q1w, q1b, nullptr, t, 2);   // nonanchor mask
    dw3x3_squeeze_k<<<dim3(Hh, Bn * Cd), Wh>>>(t, q2w, q2b, qs, 1);          // nonanchor squeeze
    conv1x1_v2_k<64, 64, 64, 0><<<g1, 256>>>(x1, k1w, k1b, nullptr, t, 1);   // anchor mask
    dw3x3_squeeze_k<<<dim3(Hh, Bn * Cd), Wh>>>(t, k2w, k2b, ks, 0);          // anchor squeeze
    conv1x1_v2_k<64, 64, 64, 0><<<g1, 256>>>(x2, v1w, v1b, nullptr, t, 0);   // no mask
    dw3x3_squeeze_k<<<dim3(Hh, Bn * Cd), Wh>>>(t, v2w, v2b, vs, 0);          // anchor squeeze

    // k softmax (in place); q softmax fused into att_k
    softmax_rows_k<<<Bn * Cd, 256>>>(ks);

    // ctx partials then squeezed att (q-softmax fused)
    ctx_k<<<dim3(Bn * 4, 8), 256>>>(ks, vs);
    att_k<<<dim3(Nh / 256, Bn * 4), 256>>>(qs, att);

    // attention = sparse conv5x5(att)
    conv5x5_sp_k<<<dim3(Ww / 16, Hh / 16, Bn * 8), 256>>>(att, rw, rb, attn);

    // MLP: m1 (gelu) -> dw3x3 (gelu) -> m3 (+ residual)
    conv1x1_v2_k<128, 256, 128, 1><<<dim3(HWC / 128, 2, Bn), 256>>>(attn, m1w, m1b, nullptr, m1, 0);
    dw3x3_gelu_k<<<dim3(Hh, Bn * 256), Ww>>>(m1, m2w, m2b, m2);
    conv1x1_v2_k<256, 128, 128, 2><<<dim3(HWC / 128, 1, Bn), 256>>>(m2, m3w, m3b, attn, out, 0);
}